// round 1
// baseline (speedup 1.0000x reference)
#include <cuda_runtime.h>
#include <math.h>

#define S_LEN 2048
#define DM    1024
#define NH    16
#define DH    64
#define BATCH 2
#define MROWS (BATCH * S_LEN)   // 4096

// ---- scratch (device globals; no allocation allowed) ----
__device__ float g_Q[BATCH * NH * S_LEN * DH];     // [B,H,S,Dh]
__device__ float g_K[BATCH * NH * S_LEN * DH];
__device__ float g_V[BATCH * NH * S_LEN * DH];
__device__ float g_attn[MROWS * DM];               // [B*S, H*Dh]
__device__ float g_proj[MROWS * DM];               // attn @ w_o

// ============================================================
// 128x128x8 tiled SGEMM, 256 threads, 8x8 micro-tile.
// MODE 0: C row-major [M,N].  MODE 1: scatter to [B,H,S,Dh].
// ============================================================
template <int MODE>
__global__ __launch_bounds__(256)
void gemm_kernel(const float* __restrict__ A, const float* __restrict__ B,
                 float* __restrict__ C, int M, int N, int K) {
    __shared__ float As[8][128];
    __shared__ float Bs[8][128];

    const int tid = threadIdx.x;
    const int m0 = blockIdx.y * 128;
    const int n0 = blockIdx.x * 128;
    const int tx = tid & 15;
    const int ty = tid >> 4;

    const int arow = tid >> 1;          // 0..127
    const int acol = (tid & 1) * 4;     // 0 or 4
    const int brow = tid >> 5;          // 0..7
    const int bcol = (tid & 31) * 4;

    const float* Aptr = A + (size_t)(m0 + arow) * K + acol;
    const float* Bptr = B + (size_t)brow * N + n0 + bcol;

    float acc[8][8];
#pragma unroll
    for (int i = 0; i < 8; i++)
#pragma unroll
        for (int j = 0; j < 8; j++) acc[i][j] = 0.f;

    for (int k0 = 0; k0 < K; k0 += 8) {
        float4 av = *(const float4*)(Aptr + k0);
        float4 bv = *(const float4*)(Bptr + (size_t)k0 * N);
        As[acol + 0][arow] = av.x;
        As[acol + 1][arow] = av.y;
        As[acol + 2][arow] = av.z;
        As[acol + 3][arow] = av.w;
        *(float4*)&Bs[brow][bcol] = bv;
        __syncthreads();

#pragma unroll
        for (int kk = 0; kk < 8; kk++) {
            float a[8], b[8];
            *(float4*)(a)     = *(const float4*)&As[kk][ty * 8];
            *(float4*)(a + 4) = *(const float4*)&As[kk][ty * 8 + 4];
            *(float4*)(b)     = *(const float4*)&Bs[kk][tx * 8];
            *(float4*)(b + 4) = *(const float4*)&Bs[kk][tx * 8 + 4];
#pragma unroll
            for (int i = 0; i < 8; i++)
#pragma unroll
                for (int j = 0; j < 8; j++) acc[i][j] = fmaf(a[i], b[j], acc[i][j]);
        }
        __syncthreads();
    }

#pragma unroll
    for (int i = 0; i < 8; i++) {
        const int m = m0 + ty * 8 + i;
#pragma unroll
        for (int j = 0; j < 8; j++) {
            const int n = n0 + tx * 8 + j;
            if (MODE == 0) {
                C[(size_t)m * N + n] = acc[i][j];
            } else {
                // m = b*2048 + s ; n = h*64 + d  ->  [B,H,S,Dh]
                const int b = m >> 11, s = m & 2047;
                const int h = n >> 6,  d = n & 63;
                C[((((size_t)b * NH + h) * S_LEN) + s) * DH + d] = acc[i][j];
            }
        }
    }
}

// ============================================================
// Flash attention: BM=BN=64, Dh=64, 256 threads (16x16, 4x4 micro),
// online softmax, causal tile skip.  Dynamic smem ~67KB.
// ============================================================
__global__ __launch_bounds__(256)
void attn_kernel(float* __restrict__ O) {
    extern __shared__ float sm[];
    float* Qs = sm;                 // 64*65
    float* Ks = Qs + 64 * 65;
    float* Vs = Ks + 64 * 65;
    float* Sp = Vs + 64 * 65;
    float* rm = Sp + 64 * 65;       // 64
    float* rl = rm + 64;
    float* rs = rl + 64;

    const int qt = blockIdx.x;      // query tile 0..31
    const int bh = blockIdx.y;      // b*16 + h
    const float* Qg = g_Q + (size_t)bh * S_LEN * DH;
    const float* Kg = g_K + (size_t)bh * S_LEN * DH;
    const float* Vg = g_V + (size_t)bh * S_LEN * DH;

    const int tid = threadIdx.x;
    const int tx = tid & 15;
    const int ty = tid >> 4;

    for (int e = tid; e < 64 * 64; e += 256) {
        int i = e >> 6, d = e & 63;
        Qs[i * 65 + d] = Qg[(size_t)(qt * 64 + i) * DH + d];
    }
    if (tid < 64) { rm[tid] = -1e30f; rl[tid] = 0.f; }

    float acc[4][4];
#pragma unroll
    for (int i = 0; i < 4; i++)
#pragma unroll
        for (int j = 0; j < 4; j++) acc[i][j] = 0.f;

    for (int kt = 0; kt <= qt; kt++) {
        for (int e = tid; e < 64 * 64; e += 256) {
            int i = e >> 6, d = e & 63;
            Ks[i * 65 + d] = Kg[(size_t)(kt * 64 + i) * DH + d];
            Vs[i * 65 + d] = Vg[(size_t)(kt * 64 + i) * DH + d];
        }
        __syncthreads();

        // scores: S = (Q @ K^T) * 0.125, causal mask -1e7
        float s[4][4];
#pragma unroll
        for (int i = 0; i < 4; i++)
#pragma unroll
            for (int j = 0; j < 4; j++) s[i][j] = 0.f;

        for (int d = 0; d < 64; d++) {
            float a[4], b[4];
#pragma unroll
            for (int i = 0; i < 4; i++) a[i] = Qs[(ty * 4 + i) * 65 + d];
#pragma unroll
            for (int j = 0; j < 4; j++) b[j] = Ks[(tx * 4 + j) * 65 + d];
#pragma unroll
            for (int i = 0; i < 4; i++)
#pragma unroll
                for (int j = 0; j < 4; j++) s[i][j] = fmaf(a[i], b[j], s[i][j]);
        }
#pragma unroll
        for (int i = 0; i < 4; i++) {
            const int qg = qt * 64 + ty * 4 + i;
#pragma unroll
            for (int j = 0; j < 4; j++) {
                const int kg = kt * 64 + tx * 4 + j;
                float v = s[i][j] * 0.125f;
                if (kg > qg) v = -10000000.0f;
                Sp[(ty * 4 + i) * 65 + tx * 4 + j] = v;
            }
        }
        __syncthreads();

        // online softmax row update (one thread per row)
        if (tid < 64) {
            const int r = tid;
            float mo = rm[r];
            float mx = mo;
            for (int j = 0; j < 64; j++) mx = fmaxf(mx, Sp[r * 65 + j]);
            float sc = __expf(mo - mx);
            float sum = 0.f;
            for (int j = 0; j < 64; j++) {
                float p = __expf(Sp[r * 65 + j] - mx);
                Sp[r * 65 + j] = p;
                sum += p;
            }
            rl[r] = rl[r] * sc + sum;
            rm[r] = mx;
            rs[r] = sc;
        }
        __syncthreads();

        // rescale accumulators, then acc += P @ V
        float scl[4];
#pragma unroll
        for (int i = 0; i < 4; i++) scl[i] = rs[ty * 4 + i];
#pragma unroll
        for (int i = 0; i < 4; i++)
#pragma unroll
            for (int j = 0; j < 4; j++) acc[i][j] *= scl[i];

        for (int kk = 0; kk < 64; kk++) {
            float p[4], v[4];
#pragma unroll
            for (int i = 0; i < 4; i++) p[i] = Sp[(ty * 4 + i) * 65 + kk];
#pragma unroll
            for (int j = 0; j < 4; j++) v[j] = Vs[kk * 65 + tx * 4 + j];
#pragma unroll
            for (int i = 0; i < 4; i++)
#pragma unroll
                for (int j = 0; j < 4; j++) acc[i][j] = fmaf(p[i], v[j], acc[i][j]);
        }
        __syncthreads();
    }

    // write normalized output to merged-head layout [B*S, H*Dh]
    const int b = bh >> 4, h = bh & 15;
#pragma unroll
    for (int i = 0; i < 4; i++) {
        const int r = ty * 4 + i;
        const float inv = 1.f / rl[r];
        const int q = qt * 64 + r;
#pragma unroll
        for (int j = 0; j < 4; j++) {
            const int c = tx * 4 + j;
            O[((size_t)b * S_LEN + q) * DM + h * DH + c] = acc[i][j] * inv;
        }
    }
}

// ============================================================
// residual + LayerNorm: out = LN(proj + x) * gamma + beta
// one block (256 thr) per row of 1024
// ============================================================
__global__ __launch_bounds__(256)
void ln_kernel(const float* __restrict__ P, const float* __restrict__ X,
               const float* __restrict__ gamma, const float* __restrict__ beta,
               float* __restrict__ out) {
    __shared__ float red[9];
    const int row = blockIdx.x;
    const int tid = threadIdx.x;
    const float* p = P + (size_t)row * DM;
    const float* x = X + (size_t)row * DM;

    float y[4];
    float sum = 0.f;
#pragma unroll
    for (int u = 0; u < 4; u++) {
        const int c = tid + u * 256;
        y[u] = p[c] + x[c];
        sum += y[u];
    }
    // block reduce (sum)
    for (int o = 16; o; o >>= 1) sum += __shfl_xor_sync(0xffffffffu, sum, o);
    const int w = tid >> 5, l = tid & 31;
    if (l == 0) red[w] = sum;
    __syncthreads();
    if (w == 0) {
        float t = (l < 8) ? red[l] : 0.f;
        for (int o = 4; o; o >>= 1) t += __shfl_xor_sync(0xffffffffu, t, o);
        if (l == 0) red[8] = t;
    }
    __syncthreads();
    const float mu = red[8] * (1.f / DM);
    __syncthreads();

    float vs = 0.f;
#pragma unroll
    for (int u = 0; u < 4; u++) {
        const float d = y[u] - mu;
        vs += d * d;
    }
    for (int o = 16; o; o >>= 1) vs += __shfl_xor_sync(0xffffffffu, vs, o);
    if (l == 0) red[w] = vs;
    __syncthreads();
    if (w == 0) {
        float t = (l < 8) ? red[l] : 0.f;
        for (int o = 4; o; o >>= 1) t += __shfl_xor_sync(0xffffffffu, t, o);
        if (l == 0) red[8] = t;
    }
    __syncthreads();
    const float var = red[8] * (1.f / DM);
    const float inv = rsqrtf(var + 1e-5f);

#pragma unroll
    for (int u = 0; u < 4; u++) {
        const int c = tid + u * 256;
        out[(size_t)row * DM + c] = (y[u] - mu) * inv * gamma[c] + beta[c];
    }
}

// ============================================================
extern "C" void kernel_launch(void* const* d_in, const int* in_sizes, int n_in,
                              void* d_out, int out_size) {
    const float* x     = (const float*)d_in[0];
    const float* wq    = (const float*)d_in[1];
    const float* wk    = (const float*)d_in[2];
    const float* wv    = (const float*)d_in[3];
    const float* wo    = (const float*)d_in[4];
    const float* gamma = (const float*)d_in[5];
    const float* beta  = (const float*)d_in[6];
    float* out = (float*)d_out;

    void *pQ, *pK, *pV, *pA, *pP;
    cudaGetSymbolAddress(&pQ, g_Q);
    cudaGetSymbolAddress(&pK, g_K);
    cudaGetSymbolAddress(&pV, g_V);
    cudaGetSymbolAddress(&pA, g_attn);
    cudaGetSymbolAddress(&pP, g_proj);

    const dim3 gdim(DM / 128, MROWS / 128);   // (8, 32)

    gemm_kernel<1><<<gdim, 256>>>(x, wq, (float*)pQ, MROWS, DM, DM);
    gemm_kernel<1><<<gdim, 256>>>(x, wk, (float*)pK, MROWS, DM, DM);
    gemm_kernel<1><<<gdim, 256>>>(x, wv, (float*)pV, MROWS, DM, DM);

    const size_t smem = (4 * 64 * 65 + 3 * 64) * sizeof(float);  // 67328 B
    cudaFuncSetAttribute(attn_kernel, cudaFuncAttributeMaxDynamicSharedMemorySize,
                         (int)smem);
    attn_kernel<<<dim3(S_LEN / 64, BATCH * NH), 256, smem>>>((float*)pA);

    gemm_kernel<0><<<gdim, 256>>>((const float*)pA, wo, (float*)pP, MROWS, DM, DM);

    ln_kernel<<<MROWS, 256>>>((const float*)pP, x, gamma, beta, out);
}

// round 9
// speedup vs baseline: 1.8935x; 1.8935x over previous
#include <cuda_runtime.h>
#include <cuda_bf16.h>
#include <cstdint>
#include <math.h>

#define S_LEN 2048
#define DM    1024
#define NH    16
#define DH    64
#define BATCH 2
#define MROWS (BATCH * S_LEN)   // 4096

using bf16 = __nv_bfloat16;

// ================= helpers =================
__device__ __forceinline__ uint32_t smem_to_u32(const void* p) {
    uint32_t a;
    asm("{ .reg .u64 t; cvta.to.shared.u64 t, %1; cvt.u32.u64 %0, t; }" : "=r"(a) : "l"(p));
    return a;
}
__device__ __forceinline__ void cp_async16(uint32_t saddr, const void* gaddr) {
    asm volatile("cp.async.cg.shared.global [%0], [%1], 16;" :: "r"(saddr), "l"(gaddr));
}
__device__ __forceinline__ void ldsm_x4(uint32_t* r, uint32_t addr) {
    asm volatile("ldmatrix.sync.aligned.m8n8.x4.shared.b16 {%0,%1,%2,%3}, [%4];"
                 : "=r"(r[0]), "=r"(r[1]), "=r"(r[2]), "=r"(r[3]) : "r"(addr));
}
__device__ __forceinline__ void ldsm_x2(uint32_t* r, uint32_t addr) {
    asm volatile("ldmatrix.sync.aligned.m8n8.x2.shared.b16 {%0,%1}, [%2];"
                 : "=r"(r[0]), "=r"(r[1]) : "r"(addr));
}
__device__ __forceinline__ void ldsm_x2t(uint32_t* r, uint32_t addr) {
    asm volatile("ldmatrix.sync.aligned.m8n8.x2.trans.shared.b16 {%0,%1}, [%2];"
                 : "=r"(r[0]), "=r"(r[1]) : "r"(addr));
}
// D += A(16x16 bf16, row) * B(16x8 bf16, col), fp32 acc
__device__ __forceinline__ void mma16816(float* d, const uint32_t* a, const uint32_t* b) {
    asm volatile(
        "mma.sync.aligned.m16n8k16.row.col.f32.bf16.bf16.f32 "
        "{%0,%1,%2,%3}, {%4,%5,%6,%7}, {%8,%9}, {%0,%1,%2,%3};\n"
        : "+f"(d[0]), "+f"(d[1]), "+f"(d[2]), "+f"(d[3])
        : "r"(a[0]), "r"(a[1]), "r"(a[2]), "r"(a[3]), "r"(b[0]), "r"(b[1]));
}

// ---- scratch (device globals) ----
__device__ bf16 g_Qhi[BATCH * NH * S_LEN * DH];
__device__ bf16 g_Qlo[BATCH * NH * S_LEN * DH];
__device__ bf16 g_Khi[BATCH * NH * S_LEN * DH];
__device__ bf16 g_Klo[BATCH * NH * S_LEN * DH];
__device__ bf16 g_Vhi[BATCH * NH * S_LEN * DH];
__device__ bf16 g_Vlo[BATCH * NH * S_LEN * DH];
__device__ bf16 g_xhi[MROWS * DM];
__device__ bf16 g_xlo[MROWS * DM];
__device__ bf16 g_ahi[MROWS * DM];
__device__ bf16 g_alo[MROWS * DM];
__device__ bf16 g_wThi[4][DM * DM];   // q,k,v,o  ([N,K] layout)
__device__ bf16 g_wTlo[4][DM * DM];
__device__ float g_proj[MROWS * DM];

// ============================================================
// fp32 -> bf16 hi/lo split (same layout)
// ============================================================
__global__ __launch_bounds__(256)
void cvt_hilo(const float* __restrict__ in, bf16* __restrict__ hi,
              bf16* __restrict__ lo) {
    const int i = blockIdx.x * 256 + threadIdx.x;
    const float v = in[i];
    const bf16 h = __float2bfloat16(v);
    hi[i] = h;
    lo[i] = __float2bfloat16(v - __bfloat162float(h));
}

// w [K=1024, N=1024] fp32 -> wT hi/lo [N, K] bf16
__global__ __launch_bounds__(256)
void cvt_wT(const float* __restrict__ w, bf16* __restrict__ hiT,
            bf16* __restrict__ loT) {
    const int i = blockIdx.x * 256 + threadIdx.x;   // i = n*1024 + k
    const int k = i & 1023;
    const int n = i >> 10;
    const float v = w[(size_t)k * DM + n];
    const bf16 h = __float2bfloat16(v);
    hiT[i] = h;
    loT[i] = __float2bfloat16(v - __bfloat162float(h));
}

// ============================================================
// HMMA split-bf16 GEMM: C[4096,1024] = A @ B^T (B stored [N,K]).
// D = Ahi*Bhi + Ahi*Blo + Alo*Bhi, fp32 accumulate.
// 128x128 block tile, K-tile 32, 8 warps (2x4), warp 64x32.
// cp.async double buffer. smem row stride 40 bf16 (80B).
// MODE 0: fp32 C row-major.  MODE 1: bf16 hi/lo scatter to [B,H,S,Dh].
// ============================================================
template <int MODE>
__global__ __launch_bounds__(256)
void mma_gemm(const bf16* __restrict__ Ahi, const bf16* __restrict__ Alo,
              const bf16* __restrict__ Bhi, const bf16* __restrict__ Blo,
              float* __restrict__ C, bf16* __restrict__ Chi, bf16* __restrict__ Clo)
{
    extern __shared__ char smd[];
    const int tid = threadIdx.x;
    const int lane = tid & 31, wid = tid >> 5;
    const int wm = wid >> 2, wn = wid & 3;
    const int m0 = blockIdx.y * 128, n0 = blockIdx.x * 128;
    const uint32_t sb = smem_to_u32(smd);

    const bf16* srcs[4] = { Ahi + (size_t)m0 * DM, Alo + (size_t)m0 * DM,
                            Bhi + (size_t)n0 * DM, Blo + (size_t)n0 * DM };

    auto prefetch = [&](int kt) {
        const uint32_t bb = sb + (kt & 1) * 40960;
        const int k0 = kt * 32;
#pragma unroll
        for (int t = 0; t < 4; t++) {
            const bf16* s = srcs[t] + k0;
            const uint32_t tb = bb + t * 10240;
#pragma unroll
            for (int i = 0; i < 2; i++) {
                const int idx = i * 256 + tid;
                const int r = idx >> 2, c = idx & 3;
                cp_async16(tb + r * 80 + c * 16, s + (size_t)r * DM + c * 8);
            }
        }
        asm volatile("cp.async.commit_group;");
    };

    prefetch(0);
    prefetch(1);

    float acc[4][4][4];
#pragma unroll
    for (int mt = 0; mt < 4; mt++)
#pragma unroll
        for (int nt = 0; nt < 4; nt++)
#pragma unroll
            for (int e = 0; e < 4; e++) acc[mt][nt][e] = 0.f;

    const int KT = DM / 32;   // 32
    for (int kt = 0; kt < KT; kt++) {
        if (kt == KT - 1) asm volatile("cp.async.wait_group 0;" ::: "memory");
        else              asm volatile("cp.async.wait_group 1;" ::: "memory");
        __syncthreads();
        const uint32_t bb = sb + (kt & 1) * 40960;
#pragma unroll
        for (int ks = 0; ks < 2; ks++) {
            const int kk = ks * 16;
            uint32_t ah[4][4], al[4][4];
            const uint32_t acol = (uint32_t)(kk + (lane >> 4) * 8) * 2;
#pragma unroll
            for (int mt = 0; mt < 4; mt++) {
                const uint32_t ra = bb + (uint32_t)(wm * 64 + mt * 16 + (lane & 15)) * 80 + acol;
                ldsm_x4(ah[mt], ra);
                ldsm_x4(al[mt], ra + 10240);
            }
#pragma unroll
            for (int nt = 0; nt < 4; nt++) {
                uint32_t bhf[2], blf[2];
                const uint32_t rb = bb + 20480
                    + (uint32_t)(wn * 32 + nt * 8 + (lane & 7)) * 80
                    + (uint32_t)(kk + ((lane >> 3) & 1) * 8) * 2;
                ldsm_x2(bhf, rb);
                ldsm_x2(blf, rb + 10240);
#pragma unroll
                for (int mt = 0; mt < 4; mt++) {
                    mma16816(acc[mt][nt], ah[mt], bhf);
                    mma16816(acc[mt][nt], ah[mt], blf);
                    mma16816(acc[mt][nt], al[mt], bhf);
                }
            }
        }
        __syncthreads();
        if (kt + 2 < KT) prefetch(kt + 2);
    }

#pragma unroll
    for (int mt = 0; mt < 4; mt++)
#pragma unroll
    for (int nt = 0; nt < 4; nt++) {
        const int r0 = m0 + wm * 64 + mt * 16 + (lane >> 2);
        const int c0 = n0 + wn * 32 + nt * 8 + (lane & 3) * 2;
#pragma unroll
        for (int e = 0; e < 4; e++) {
            const int r = r0 + (e >> 1) * 8;
            const int c = c0 + (e & 1);
            const float v = acc[mt][nt][e];
            if (MODE == 0) {
                C[(size_t)r * DM + c] = v;
            } else {
                const int b = r >> 11, s = r & 2047;
                const int h = c >> 6, d = c & 63;
                const size_t o = (((size_t)(b * NH + h)) * S_LEN + s) * DH + d;
                const bf16 hv = __float2bfloat16(v);
                Chi[o] = hv;
                Clo[o] = __float2bfloat16(v - __bfloat162float(hv));
            }
        }
    }
}

// ============================================================
// HMMA flash attention: 64x64 tiles, Dh=64, 8 warps (2x4),
// split-bf16 3-pass for QK^T and PV, fp32 online softmax.
// K/V double-buffered via cp.async.
// ============================================================
__global__ __launch_bounds__(256)
void attn_kernel() {
    extern __shared__ char smd[];
    const int tid = threadIdx.x, lane = tid & 31, wid = tid >> 5;
    const int wm = wid >> 2, wn = wid & 3;
    const int qt = blockIdx.x, bh = blockIdx.y;
    const int b = bh >> 4, h = bh & 15;
    const uint32_t sb = smem_to_u32(smd);

    // byte offsets (tile = 64 rows x 72 bf16 = 9216B)
    const uint32_t QH = 0, QL = 9216;
    const uint32_t KV0 = 18432, KVSZ = 36864;   // per buf: Khi,Klo,Vhi,Vlo
    const uint32_t SPO = 92160;                 // fp32 64x66
    const uint32_t PHO = 109056, PLO = 118272;
    const uint32_t RMO = 127488, RLO = 127744, RSO = 128000;

    float* Sp = (float*)(smd + SPO);
    bf16* Phi = (bf16*)(smd + PHO);
    bf16* Plo = (bf16*)(smd + PLO);
    float* rm = (float*)(smd + RMO);
    float* rl = (float*)(smd + RLO);
    float* rs = (float*)(smd + RSO);

    // load Q tiles (hi/lo)
    {
        const size_t qoff = ((size_t)bh * S_LEN + (size_t)qt * 64) * DH;
        const bf16* qh = g_Qhi + qoff;
        const bf16* ql = g_Qlo + qoff;
#pragma unroll
        for (int i = 0; i < 2; i++) {
            const int idx = i * 256 + tid;
            const int r = idx >> 3, c = idx & 7;
            cp_async16(sb + QH + r * 144 + c * 16, qh + r * 64 + c * 8);
            cp_async16(sb + QL + r * 144 + c * 16, ql + r * 64 + c * 8);
        }
    }
    auto kvload = [&](int kt) {
        const uint32_t bb = sb + KV0 + (kt & 1) * KVSZ;
        const size_t off = ((size_t)bh * S_LEN + (size_t)kt * 64) * DH;
        const bf16* srcs[4] = { g_Khi + off, g_Klo + off, g_Vhi + off, g_Vlo + off };
#pragma unroll
        for (int t = 0; t < 4; t++) {
            const uint32_t tb = bb + t * 9216;
            const bf16* s = srcs[t];
#pragma unroll
            for (int i = 0; i < 2; i++) {
                const int idx = i * 256 + tid;
                const int r = idx >> 3, c = idx & 7;
                cp_async16(tb + r * 144 + c * 16, s + r * 64 + c * 8);
            }
        }
        asm volatile("cp.async.commit_group;");
    };
    kvload(0);

    if (tid < 64) { rm[tid] = -1e30f; rl[tid] = 0.f; }

    float oacc[2][2][4];
#pragma unroll
    for (int mt = 0; mt < 2; mt++)
#pragma unroll
        for (int nt = 0; nt < 2; nt++)
#pragma unroll
            for (int e = 0; e < 4; e++) oacc[mt][nt][e] = 0.f;

    for (int kt = 0; kt <= qt; kt++) {
        if (kt < qt) {
            kvload(kt + 1);
            asm volatile("cp.async.wait_group 1;" ::: "memory");
        } else {
            asm volatile("cp.async.wait_group 0;" ::: "memory");
        }
        __syncthreads();
        const uint32_t kb = sb + KV0 + (kt & 1) * KVSZ;   // Khi
        const uint32_t vb = kb + 18432;                    // Vhi

        // ---- S = Q @ K^T (3-pass split) ----
        float sacc[2][2][4];
#pragma unroll
        for (int mt = 0; mt < 2; mt++)
#pragma unroll
            for (int nt = 0; nt < 2; nt++)
#pragma unroll
                for (int e = 0; e < 4; e++) sacc[mt][nt][e] = 0.f;

#pragma unroll
        for (int ks = 0; ks < 4; ks++) {
            const int kk = ks * 16;
            uint32_t qhf[2][4], qlf[2][4];
            const uint32_t acol = (uint32_t)(kk + (lane >> 4) * 8) * 2;
#pragma unroll
            for (int mt = 0; mt < 2; mt++) {
                const uint32_t ra = sb + QH + (uint32_t)(wm * 32 + mt * 16 + (lane & 15)) * 144 + acol;
                ldsm_x4(qhf[mt], ra);
                ldsm_x4(qlf[mt], ra + 9216);
            }
#pragma unroll
            for (int nt = 0; nt < 2; nt++) {
                uint32_t khf[2], klf[2];
                const uint32_t rb = kb + (uint32_t)(wn * 16 + nt * 8 + (lane & 7)) * 144
                                    + (uint32_t)(kk + ((lane >> 3) & 1) * 8) * 2;
                ldsm_x2(khf, rb);
                ldsm_x2(klf, rb + 9216);
#pragma unroll
                for (int mt = 0; mt < 2; mt++) {
                    mma16816(sacc[mt][nt], qhf[mt], khf);
                    mma16816(sacc[mt][nt], qhf[mt], klf);
                    mma16816(sacc[mt][nt], qlf[mt], khf);
                }
            }
        }
        // scale + causal mask + store to smem
#pragma unroll
        for (int mt = 0; mt < 2; mt++)
#pragma unroll
        for (int nt = 0; nt < 2; nt++) {
            const int r0 = wm * 32 + mt * 16 + (lane >> 2);
            const int c0 = wn * 16 + nt * 8 + (lane & 3) * 2;
#pragma unroll
            for (int e = 0; e < 4; e++) {
                const int r = r0 + (e >> 1) * 8;
                const int c = c0 + (e & 1);
                float v = sacc[mt][nt][e] * 0.125f;
                if (kt * 64 + c > qt * 64 + r) v = -10000000.0f;
                Sp[r * 66 + c] = v;
            }
        }
        __syncthreads();

        // ---- online softmax (4 threads/row) -> P hi/lo ----
        {
            const int r = tid >> 2, sub = tid & 3;
            const float mo = rm[r];
            float mx = mo;
            float* sp = Sp + r * 66 + sub * 16;
#pragma unroll
            for (int j = 0; j < 16; j++) mx = fmaxf(mx, sp[j]);
            mx = fmaxf(mx, __shfl_xor_sync(0xffffffffu, mx, 1));
            mx = fmaxf(mx, __shfl_xor_sync(0xffffffffu, mx, 2));
            float sum = 0.f;
            bf16* ph = Phi + r * 72 + sub * 16;
            bf16* pl = Plo + r * 72 + sub * 16;
#pragma unroll
            for (int j = 0; j < 16; j++) {
                const float p = __expf(sp[j] - mx);
                sum += p;
                const bf16 hv = __float2bfloat16(p);
                ph[j] = hv;
                pl[j] = __float2bfloat16(p - __bfloat162float(hv));
            }
            sum += __shfl_xor_sync(0xffffffffu, sum, 1);
            sum += __shfl_xor_sync(0xffffffffu, sum, 2);
            if (sub == 0) {
                const float sc = __expf(mo - mx);
                rl[r] = rl[r] * sc + sum;
                rm[r] = mx;
                rs[r] = sc;
            }
        }
        __syncthreads();

        // ---- rescale O, then O += P @ V (3-pass split) ----
#pragma unroll
        for (int mt = 0; mt < 2; mt++) {
            const float s0 = rs[wm * 32 + mt * 16 + (lane >> 2)];
            const float s1 = rs[wm * 32 + mt * 16 + (lane >> 2) + 8];
#pragma unroll
            for (int nt = 0; nt < 2; nt++) {
                oacc[mt][nt][0] *= s0; oacc[mt][nt][1] *= s0;
                oacc[mt][nt][2] *= s1; oacc[mt][nt][3] *= s1;
            }
        }
#pragma unroll
        for (int ks = 0; ks < 4; ks++) {
            const int kk = ks * 16;
            uint32_t phf[2][4], plf[2][4];
            const uint32_t acol = (uint32_t)(kk + (lane >> 4) * 8) * 2;
#pragma unroll
            for (int mt = 0; mt < 2; mt++) {
                const uint32_t ra = sb + PHO + (uint32_t)(wm * 32 + mt * 16 + (lane & 15)) * 144 + acol;
                ldsm_x4(phf[mt], ra);
                ldsm_x4(plf[mt], ra + 9216);
            }
#pragma unroll
            for (int nt = 0; nt < 2; nt++) {
                uint32_t vhf[2], vlf[2];
                const uint32_t rb = vb + (uint32_t)(kk + (lane & 15)) * 144
                                    + (uint32_t)(wn * 16 + nt * 8) * 2;
                ldsm_x2t(vhf, rb);
                ldsm_x2t(vlf, rb + 9216);
#pragma unroll
                for (int mt = 0; mt < 2; mt++) {
                    mma16816(oacc[mt][nt], phf[mt], vhf);
                    mma16816(oacc[mt][nt], phf[mt], vlf);
                    mma16816(oacc[mt][nt], plf[mt], vhf);
                }
            }
        }
        __syncthreads();
    }

    // ---- epilogue: O / l  -> bf16 hi/lo merged-head layout ----
#pragma unroll
    for (int mt = 0; mt < 2; mt++) {
        const int rr0 = wm * 32 + mt * 16 + (lane >> 2);
        const float i0 = 1.f / rl[rr0];
        const float i1 = 1.f / rl[rr0 + 8];
#pragma unroll
        for (int nt = 0; nt < 2; nt++) {
            const int c0 = wn * 16 + nt * 8 + (lane & 3) * 2;
#pragma unroll
            for (int e = 0; e < 4; e++) {
                const int r = rr0 + (e >> 1) * 8;
                const int c = c0 + (e & 1);
                const float v = oacc[mt][nt][e] * ((e >> 1) ? i1 : i0);
                const size_t m = (size_t)b * S_LEN + (size_t)qt * 64 + r;
                const size_t n = (size_t)h * 64 + c;
                const bf16 hv = __float2bfloat16(v);
                g_ahi[m * DM + n] = hv;
                g_alo[m * DM + n] = __float2bfloat16(v - __bfloat162float(hv));
            }
        }
    }
}

// ============================================================
// residual + LayerNorm
// ============================================================
__global__ __launch_bounds__(256)
void ln_kernel(const float* __restrict__ P, const float* __restrict__ X,
               const float* __restrict__ gamma, const float* __restrict__ beta,
               float* __restrict__ out) {
    __shared__ float red[9];
    const int row = blockIdx.x;
    const int tid = threadIdx.x;
    const float* p = P + (size_t)row * DM;
    const float* x = X + (size_t)row * DM;

    float y[4];
    float sum = 0.f;
#pragma unroll
    for (int u = 0; u < 4; u++) {
        const int c = tid + u * 256;
        y[u] = p[c] + x[c];
        sum += y[u];
    }
    for (int o = 16; o; o >>= 1) sum += __shfl_xor_sync(0xffffffffu, sum, o);
    const int w = tid >> 5, l = tid & 31;
    if (l == 0) red[w] = sum;
    __syncthreads();
    if (w == 0) {
        float t = (l < 8) ? red[l] : 0.f;
        for (int o = 4; o; o >>= 1) t += __shfl_xor_sync(0xffffffffu, t, o);
        if (l == 0) red[8] = t;
    }
    __syncthreads();
    const float mu = red[8] * (1.f / DM);
    __syncthreads();

    float vs = 0.f;
#pragma unroll
    for (int u = 0; u < 4; u++) {
        const float d = y[u] - mu;
        vs += d * d;
    }
    for (int o = 16; o; o >>= 1) vs += __shfl_xor_sync(0xffffffffu, vs, o);
    if (l == 0) red[w] = vs;
    __syncthreads();
    if (w == 0) {
        float t = (l < 8) ? red[l] : 0.f;
        for (int o = 4; o; o >>= 1) t += __shfl_xor_sync(0xffffffffu, t, o);
        if (l == 0) red[8] = t;
    }
    __syncthreads();
    const float var = red[8] * (1.f / DM);
    const float inv = rsqrtf(var + 1e-5f);

#pragma unroll
    for (int u = 0; u < 4; u++) {
        const int c = tid + u * 256;
        out[(size_t)row * DM + c] = (y[u] - mu) * inv * gamma[c] + beta[c];
    }
}

// ============================================================
extern "C" void kernel_launch(void* const* d_in, const int* in_sizes, int n_in,
                              void* d_out, int out_size) {
    const float* x     = (const float*)d_in[0];
    const float* wq    = (const float*)d_in[1];
    const float* wk    = (const float*)d_in[2];
    const float* wv    = (const float*)d_in[3];
    const float* wo    = (const float*)d_in[4];
    const float* gamma = (const float*)d_in[5];
    const float* beta  = (const float*)d_in[6];
    float* out = (float*)d_out;

    void *pQh, *pQl, *pKh, *pKl, *pVh, *pVl;
    void *pxhi, *pxlo, *pahi, *palo, *pwhi, *pwlo, *pP;
    cudaGetSymbolAddress(&pQh, g_Qhi);  cudaGetSymbolAddress(&pQl, g_Qlo);
    cudaGetSymbolAddress(&pKh, g_Khi);  cudaGetSymbolAddress(&pKl, g_Klo);
    cudaGetSymbolAddress(&pVh, g_Vhi);  cudaGetSymbolAddress(&pVl, g_Vlo);
    cudaGetSymbolAddress(&pxhi, g_xhi); cudaGetSymbolAddress(&pxlo, g_xlo);
    cudaGetSymbolAddress(&pahi, g_ahi); cudaGetSymbolAddress(&palo, g_alo);
    cudaGetSymbolAddress(&pwhi, g_wThi); cudaGetSymbolAddress(&pwlo, g_wTlo);
    cudaGetSymbolAddress(&pP, g_proj);

    bf16* xhi = (bf16*)pxhi;  bf16* xlo = (bf16*)pxlo;
    bf16* ahi = (bf16*)pahi;  bf16* alo = (bf16*)palo;
    bf16* whi = (bf16*)pwhi;  bf16* wlo = (bf16*)pwlo;

    // conversions
    cvt_hilo<<<(MROWS * DM) / 256, 256>>>(x, xhi, xlo);
    cvt_wT<<<(DM * DM) / 256, 256>>>(wq, whi + 0 * (size_t)DM * DM, wlo + 0 * (size_t)DM * DM);
    cvt_wT<<<(DM * DM) / 256, 256>>>(wk, whi + 1 * (size_t)DM * DM, wlo + 1 * (size_t)DM * DM);
    cvt_wT<<<(DM * DM) / 256, 256>>>(wv, whi + 2 * (size_t)DM * DM, wlo + 2 * (size_t)DM * DM);
    cvt_wT<<<(DM * DM) / 256, 256>>>(wo, whi + 3 * (size_t)DM * DM, wlo + 3 * (size_t)DM * DM);

    const int gemm_smem = 2 * 40960;   // 80 KB
    cudaFuncSetAttribute(mma_gemm<0>, cudaFuncAttributeMaxDynamicSharedMemorySize, gemm_smem);
    cudaFuncSetAttribute(mma_gemm<1>, cudaFuncAttributeMaxDynamicSharedMemorySize, gemm_smem);

    const dim3 gdim(DM / 128, MROWS / 128);   // (8, 32)
    mma_gemm<1><<<gdim, 256, gemm_smem>>>(xhi, xlo, whi + 0 * (size_t)DM * DM, wlo + 0 * (size_t)DM * DM,
                                          nullptr, (bf16*)pQh, (bf16*)pQl);
    mma_gemm<1><<<gdim, 256, gemm_smem>>>(xhi, xlo, whi + 1 * (size_t)DM * DM, wlo + 1 * (size_t)DM * DM,
                                          nullptr, (bf16*)pKh, (bf16*)pKl);
    mma_gemm<1><<<gdim, 256, gemm_smem>>>(xhi, xlo, whi + 2 * (size_t)DM * DM, wlo + 2 * (size_t)DM * DM,
                                          nullptr, (bf16*)pVh, (bf16*)pVl);

    const int attn_smem = 128256;
    cudaFuncSetAttribute(attn_kernel, cudaFuncAttributeMaxDynamicSharedMemorySize, attn_smem);
    attn_kernel<<<dim3(S_LEN / 64, BATCH * NH), 256, attn_smem>>>();

    mma_gemm<0><<<gdim, 256, gemm_smem>>>(ahi, alo, whi + 3 * (size_t)DM * DM, wlo + 3 * (size_t)DM * DM,
                                          (float*)pP, nullptr, nullptr);

    ln_kernel<<<MROWS, 256>>>((const float*)pP, x, gamma, beta, out);
}

// round 10
// speedup vs baseline: 2.4215x; 1.2788x over previous
#include <cuda_runtime.h>
#include <cuda_bf16.h>
#include <cstdint>
#include <math.h>

#define S_LEN 2048
#define DM    1024
#define NH    16
#define DH    64
#define BATCH 2
#define MROWS (BATCH * S_LEN)   // 4096

using bf16 = __nv_bfloat16;

// ================= helpers =================
__device__ __forceinline__ uint32_t smem_to_u32(const void* p) {
    uint32_t a;
    asm("{ .reg .u64 t; cvta.to.shared.u64 t, %1; cvt.u32.u64 %0, t; }" : "=r"(a) : "l"(p));
    return a;
}
__device__ __forceinline__ void cp_async16(uint32_t saddr, const void* gaddr) {
    asm volatile("cp.async.cg.shared.global [%0], [%1], 16;" :: "r"(saddr), "l"(gaddr));
}
__device__ __forceinline__ void ldsm_x4(uint32_t* r, uint32_t addr) {
    asm volatile("ldmatrix.sync.aligned.m8n8.x4.shared.b16 {%0,%1,%2,%3}, [%4];"
                 : "=r"(r[0]), "=r"(r[1]), "=r"(r[2]), "=r"(r[3]) : "r"(addr));
}
__device__ __forceinline__ void ldsm_x2(uint32_t* r, uint32_t addr) {
    asm volatile("ldmatrix.sync.aligned.m8n8.x2.shared.b16 {%0,%1}, [%2];"
                 : "=r"(r[0]), "=r"(r[1]) : "r"(addr));
}
__device__ __forceinline__ void ldsm_x2t(uint32_t* r, uint32_t addr) {
    asm volatile("ldmatrix.sync.aligned.m8n8.x2.trans.shared.b16 {%0,%1}, [%2];"
                 : "=r"(r[0]), "=r"(r[1]) : "r"(addr));
}
// D += A(16x16 bf16, row) * B(16x8 bf16, col), fp32 acc
__device__ __forceinline__ void mma16816(float* d, const uint32_t* a, const uint32_t* b) {
    asm volatile(
        "mma.sync.aligned.m16n8k16.row.col.f32.bf16.bf16.f32 "
        "{%0,%1,%2,%3}, {%4,%5,%6,%7}, {%8,%9}, {%0,%1,%2,%3};\n"
        : "+f"(d[0]), "+f"(d[1]), "+f"(d[2]), "+f"(d[3])
        : "r"(a[0]), "r"(a[1]), "r"(a[2]), "r"(a[3]), "r"(b[0]), "r"(b[1]));
}
// pack two fp32 into bf16x2 (hi part) plus residual bf16x2 (lo part)
__device__ __forceinline__ void pack_pair(float p0, float p1, uint32_t& hi, uint32_t& lo) {
    __nv_bfloat162 h = __floats2bfloat162_rn(p0, p1);   // .x = p0 (low half)
    hi = *(uint32_t*)&h;
    const float l0 = p0 - __bfloat162float(h.x);
    const float l1 = p1 - __bfloat162float(h.y);
    __nv_bfloat162 l = __floats2bfloat162_rn(l0, l1);
    lo = *(uint32_t*)&l;
}

// ---- scratch (device globals) ----
__device__ bf16 g_Qhi[BATCH * NH * S_LEN * DH];
__device__ bf16 g_Qlo[BATCH * NH * S_LEN * DH];
__device__ bf16 g_Khi[BATCH * NH * S_LEN * DH];
__device__ bf16 g_Klo[BATCH * NH * S_LEN * DH];
__device__ bf16 g_Vhi[BATCH * NH * S_LEN * DH];
__device__ bf16 g_Vlo[BATCH * NH * S_LEN * DH];
__device__ bf16 g_xhi[MROWS * DM];
__device__ bf16 g_xlo[MROWS * DM];
__device__ bf16 g_ahi[MROWS * DM];
__device__ bf16 g_alo[MROWS * DM];
__device__ bf16 g_wThi[4][DM * DM];   // q,k,v,o  ([N,K] layout)
__device__ bf16 g_wTlo[4][DM * DM];
__device__ float g_proj[MROWS * DM];

// ============================================================
// fp32 -> bf16 hi/lo split (same layout)
// ============================================================
__global__ __launch_bounds__(256)
void cvt_hilo(const float* __restrict__ in, bf16* __restrict__ hi,
              bf16* __restrict__ lo) {
    const int i = blockIdx.x * 256 + threadIdx.x;
    const float v = in[i];
    const bf16 h = __float2bfloat16(v);
    hi[i] = h;
    lo[i] = __float2bfloat16(v - __bfloat162float(h));
}

// w [K=1024, N=1024] fp32 -> wT hi/lo [N, K] bf16
__global__ __launch_bounds__(256)
void cvt_wT(const float* __restrict__ w, bf16* __restrict__ hiT,
            bf16* __restrict__ loT) {
    const int i = blockIdx.x * 256 + threadIdx.x;   // i = n*1024 + k
    const int k = i & 1023;
    const int n = i >> 10;
    const float v = w[(size_t)k * DM + n];
    const bf16 h = __float2bfloat16(v);
    hiT[i] = h;
    loT[i] = __float2bfloat16(v - __bfloat162float(h));
}

// ============================================================
// HMMA split-bf16 GEMM: C[4096,1024] = A @ B^T (B stored [N,K]).
// D = Ahi*Bhi + Ahi*Blo + Alo*Bhi, fp32 accumulate.
// 128x128 block tile, K-tile 32, 8 warps (2x4), warp 64x32.
// cp.async double buffer. smem row stride 40 bf16 (80B).
// MODE 0: fp32 C row-major.  MODE 1: bf16 hi/lo scatter to [B,H,S,Dh].
// ============================================================
template <int MODE>
__global__ __launch_bounds__(256)
void mma_gemm(const bf16* __restrict__ Ahi, const bf16* __restrict__ Alo,
              const bf16* __restrict__ Bhi, const bf16* __restrict__ Blo,
              float* __restrict__ C, bf16* __restrict__ Chi, bf16* __restrict__ Clo)
{
    extern __shared__ char smd[];
    const int tid = threadIdx.x;
    const int lane = tid & 31, wid = tid >> 5;
    const int wm = wid >> 2, wn = wid & 3;
    const int m0 = blockIdx.y * 128, n0 = blockIdx.x * 128;
    const uint32_t sb = smem_to_u32(smd);

    const bf16* srcs[4] = { Ahi + (size_t)m0 * DM, Alo + (size_t)m0 * DM,
                            Bhi + (size_t)n0 * DM, Blo + (size_t)n0 * DM };

    auto prefetch = [&](int kt) {
        const uint32_t bb = sb + (kt & 1) * 40960;
        const int k0 = kt * 32;
#pragma unroll
        for (int t = 0; t < 4; t++) {
            const bf16* s = srcs[t] + k0;
            const uint32_t tb = bb + t * 10240;
#pragma unroll
            for (int i = 0; i < 2; i++) {
                const int idx = i * 256 + tid;
                const int r = idx >> 2, c = idx & 3;
                cp_async16(tb + r * 80 + c * 16, s + (size_t)r * DM + c * 8);
            }
        }
        asm volatile("cp.async.commit_group;");
    };

    prefetch(0);
    prefetch(1);

    float acc[4][4][4];
#pragma unroll
    for (int mt = 0; mt < 4; mt++)
#pragma unroll
        for (int nt = 0; nt < 4; nt++)
#pragma unroll
            for (int e = 0; e < 4; e++) acc[mt][nt][e] = 0.f;

    const int KT = DM / 32;   // 32
    for (int kt = 0; kt < KT; kt++) {
        if (kt == KT - 1) asm volatile("cp.async.wait_group 0;" ::: "memory");
        else              asm volatile("cp.async.wait_group 1;" ::: "memory");
        __syncthreads();
        const uint32_t bb = sb + (kt & 1) * 40960;
#pragma unroll
        for (int ks = 0; ks < 2; ks++) {
            const int kk = ks * 16;
            uint32_t ah[4][4], al[4][4];
            const uint32_t acol = (uint32_t)(kk + (lane >> 4) * 8) * 2;
#pragma unroll
            for (int mt = 0; mt < 4; mt++) {
                const uint32_t ra = bb + (uint32_t)(wm * 64 + mt * 16 + (lane & 15)) * 80 + acol;
                ldsm_x4(ah[mt], ra);
                ldsm_x4(al[mt], ra + 10240);
            }
#pragma unroll
            for (int nt = 0; nt < 4; nt++) {
                uint32_t bhf[2], blf[2];
                const uint32_t rb = bb + 20480
                    + (uint32_t)(wn * 32 + nt * 8 + (lane & 7)) * 80
                    + (uint32_t)(kk + ((lane >> 3) & 1) * 8) * 2;
                ldsm_x2(bhf, rb);
                ldsm_x2(blf, rb + 10240);
#pragma unroll
                for (int mt = 0; mt < 4; mt++) {
                    mma16816(acc[mt][nt], ah[mt], bhf);
                    mma16816(acc[mt][nt], ah[mt], blf);
                    mma16816(acc[mt][nt], al[mt], bhf);
                }
            }
        }
        __syncthreads();
        if (kt + 2 < KT) prefetch(kt + 2);
    }

#pragma unroll
    for (int mt = 0; mt < 4; mt++)
#pragma unroll
    for (int nt = 0; nt < 4; nt++) {
        const int r0 = m0 + wm * 64 + mt * 16 + (lane >> 2);
        const int c0 = n0 + wn * 32 + nt * 8 + (lane & 3) * 2;
#pragma unroll
        for (int e = 0; e < 4; e++) {
            const int r = r0 + (e >> 1) * 8;
            const int c = c0 + (e & 1);
            const float v = acc[mt][nt][e];
            if (MODE == 0) {
                C[(size_t)r * DM + c] = v;
            } else {
                const int b = r >> 11, s = r & 2047;
                const int h = c >> 6, d = c & 63;
                const size_t o = (((size_t)(b * NH + h)) * S_LEN + s) * DH + d;
                const bf16 hv = __float2bfloat16(v);
                Chi[o] = hv;
                Clo[o] = __float2bfloat16(v - __bfloat162float(hv));
            }
        }
    }
}

// ============================================================
// FA2-style HMMA flash attention: BM=128, BN=64, Dh=64, 8 warps.
// Each warp: 16 query rows x full 64 kv cols x full 64 d.
// S acc kept in registers; softmax via quad shfl; P repacked from
// C-frag into A-frag in registers (no S/P smem round trip).
// 3-pass hi/lo split for both QK^T and PV.
// ============================================================
__global__ __launch_bounds__(256)
void attn_kernel() {
    extern __shared__ char smd[];
    const int tid = threadIdx.x, lane = tid & 31, wid = tid >> 5;
    const int qt = (int)gridDim.x - 1 - (int)blockIdx.x;   // heavy tiles first
    const int bh = blockIdx.y;
    const int b = bh >> 4, h = bh & 15;
    const int q0 = qt * 128;
    const int groupID = lane >> 2, tid4 = lane & 3;
    const uint32_t sb = smem_to_u32(smd);
    const uint32_t QHo = 0;                        // 128 x 144B
    const uint32_t KV0 = 36864, KVSZ = 36864;      // per buf: Khi,Klo,Vhi,Vlo (64x144B each)
    const int nkt = 2 * qt + 2;

    const size_t base_off = (size_t)bh * S_LEN * DH;

    // Q hi/lo loads (group 0, together with KV tile 0)
    {
        const bf16* qh = g_Qhi + base_off + (size_t)q0 * DH;
        const bf16* ql = g_Qlo + base_off + (size_t)q0 * DH;
#pragma unroll
        for (int i = 0; i < 4; i++) {
            const int idx = i * 256 + tid;
            const int r = idx >> 3, c = idx & 7;
            cp_async16(sb + QHo + r * 144 + c * 16, qh + r * 64 + c * 8);
            cp_async16(sb + QHo + 18432 + r * 144 + c * 16, ql + r * 64 + c * 8);
        }
    }
    auto kvload = [&](int kt) {
        const uint32_t bb = sb + KV0 + (kt & 1) * KVSZ;
        const size_t off = base_off + (size_t)kt * 64 * DH;
        const bf16* srcs[4] = { g_Khi + off, g_Klo + off, g_Vhi + off, g_Vlo + off };
#pragma unroll
        for (int t = 0; t < 4; t++) {
            const uint32_t tb = bb + t * 9216;
            const bf16* s = srcs[t];
#pragma unroll
            for (int i = 0; i < 2; i++) {
                const int idx = i * 256 + tid;
                const int r = idx >> 3, c = idx & 7;
                cp_async16(tb + r * 144 + c * 16, s + r * 64 + c * 8);
            }
        }
        asm volatile("cp.async.commit_group;");
    };
    kvload(0);           // G0 = Q + KV0
    kvload(1);           // G1 = KV1   (nkt >= 2 always)
    asm volatile("cp.async.wait_group 1;" ::: "memory");
    __syncthreads();

    // Hoist Q fragments for the whole kernel
    uint32_t qhf[4][4], qlf[4][4];
#pragma unroll
    for (int ks = 0; ks < 4; ks++) {
        const uint32_t ra = sb + QHo + (uint32_t)(wid * 16 + (lane & 15)) * 144
                            + (uint32_t)(ks * 16 + (lane >> 4) * 8) * 2;
        ldsm_x4(qhf[ks], ra);
        ldsm_x4(qlf[ks], ra + 18432);
    }

    float rm0 = -1e30f, rm1 = -1e30f, rl0 = 0.f, rl1 = 0.f;
    float oacc[8][4];
#pragma unroll
    for (int nt = 0; nt < 8; nt++)
#pragma unroll
        for (int e = 0; e < 4; e++) oacc[nt][e] = 0.f;

    for (int kt = 0; kt < nkt; kt++) {
        const uint32_t kb = sb + KV0 + (kt & 1) * KVSZ;
        const uint32_t vb = kb + 18432;

        // ---- S = Q @ K^T (3-pass split), 16x64 per warp ----
        float sacc[8][4];
#pragma unroll
        for (int nt = 0; nt < 8; nt++)
#pragma unroll
            for (int e = 0; e < 4; e++) sacc[nt][e] = 0.f;

#pragma unroll
        for (int ks = 0; ks < 4; ks++) {
#pragma unroll
            for (int nt = 0; nt < 8; nt++) {
                uint32_t khf[2], klf[2];
                const uint32_t rb = kb + (uint32_t)(nt * 8 + (lane & 7)) * 144
                                    + (uint32_t)(ks * 16 + ((lane >> 3) & 1) * 8) * 2;
                ldsm_x2(khf, rb);
                ldsm_x2(klf, rb + 9216);
                mma16816(sacc[nt], qhf[ks], khf);
                mma16816(sacc[nt], qhf[ks], klf);
                mma16816(sacc[nt], qlf[ks], khf);
            }
        }

        // ---- scale + causal mask (in registers) ----
        const int row0 = q0 + wid * 16 + groupID;
#pragma unroll
        for (int nt = 0; nt < 8; nt++) {
            const int c0 = kt * 64 + nt * 8 + tid4 * 2;
#pragma unroll
            for (int e = 0; e < 4; e++) {
                const int col = c0 + (e & 1);
                const int row = row0 + ((e >> 1) << 3);
                const float v = sacc[nt][e] * 0.125f;
                sacc[nt][e] = (col > row) ? -10000000.0f : v;
            }
        }

        // ---- online softmax (quad shfl, rows groupID and groupID+8) ----
        float mx0 = rm0, mx1 = rm1;
#pragma unroll
        for (int nt = 0; nt < 8; nt++) {
            mx0 = fmaxf(mx0, fmaxf(sacc[nt][0], sacc[nt][1]));
            mx1 = fmaxf(mx1, fmaxf(sacc[nt][2], sacc[nt][3]));
        }
        mx0 = fmaxf(mx0, __shfl_xor_sync(0xffffffffu, mx0, 1));
        mx0 = fmaxf(mx0, __shfl_xor_sync(0xffffffffu, mx0, 2));
        mx1 = fmaxf(mx1, __shfl_xor_sync(0xffffffffu, mx1, 1));
        mx1 = fmaxf(mx1, __shfl_xor_sync(0xffffffffu, mx1, 2));
        float s0 = 0.f, s1 = 0.f;
#pragma unroll
        for (int nt = 0; nt < 8; nt++) {
            sacc[nt][0] = __expf(sacc[nt][0] - mx0); s0 += sacc[nt][0];
            sacc[nt][1] = __expf(sacc[nt][1] - mx0); s0 += sacc[nt][1];
            sacc[nt][2] = __expf(sacc[nt][2] - mx1); s1 += sacc[nt][2];
            sacc[nt][3] = __expf(sacc[nt][3] - mx1); s1 += sacc[nt][3];
        }
        s0 += __shfl_xor_sync(0xffffffffu, s0, 1);
        s0 += __shfl_xor_sync(0xffffffffu, s0, 2);
        s1 += __shfl_xor_sync(0xffffffffu, s1, 1);
        s1 += __shfl_xor_sync(0xffffffffu, s1, 2);
        const float sc0 = __expf(rm0 - mx0), sc1 = __expf(rm1 - mx1);
        rl0 = rl0 * sc0 + s0;  rl1 = rl1 * sc1 + s1;
        rm0 = mx0;  rm1 = mx1;
#pragma unroll
        for (int nt = 0; nt < 8; nt++) {
            oacc[nt][0] *= sc0; oacc[nt][1] *= sc0;
            oacc[nt][2] *= sc1; oacc[nt][3] *= sc1;
        }

        // ---- O += P @ V: repack C-frag -> A-frag in registers ----
#pragma unroll
        for (int j = 0; j < 4; j++) {
            uint32_t ph[4], pl[4];
            pack_pair(sacc[2 * j][0],     sacc[2 * j][1],     ph[0], pl[0]);
            pack_pair(sacc[2 * j][2],     sacc[2 * j][3],     ph[1], pl[1]);
            pack_pair(sacc[2 * j + 1][0], sacc[2 * j + 1][1], ph[2], pl[2]);
            pack_pair(sacc[2 * j + 1][2], sacc[2 * j + 1][3], ph[3], pl[3]);
#pragma unroll
            for (int nt = 0; nt < 8; nt++) {
                uint32_t vhf[2], vlf[2];
                const uint32_t rb = vb + (uint32_t)(j * 16 + (lane & 15)) * 144
                                    + (uint32_t)(nt * 8) * 2;
                ldsm_x2t(vhf, rb);
                ldsm_x2t(vlf, rb + 9216);
                mma16816(oacc[nt], ph, vhf);
                mma16816(oacc[nt], ph, vlf);
                mma16816(oacc[nt], pl, vhf);
            }
        }

        // ---- pipeline next KV tile ----
        if (kt + 1 < nkt) {
            __syncthreads();   // all warps done reading buf (kt&1)
            if (kt + 2 < nkt) {
                kvload(kt + 2);
                asm volatile("cp.async.wait_group 1;" ::: "memory");
            } else {
                asm volatile("cp.async.wait_group 0;" ::: "memory");
            }
        }
    }

    // ---- epilogue: O / l  -> bf16 hi/lo merged-head layout ----
    const float inv0 = 1.f / rl0, inv1 = 1.f / rl1;
    const size_t m0 = (size_t)b * S_LEN + q0 + wid * 16 + groupID;
    const size_t m1 = m0 + 8;
#pragma unroll
    for (int nt = 0; nt < 8; nt++) {
        const int n = h * 64 + nt * 8 + tid4 * 2;
        {
            const float v0 = oacc[nt][0] * inv0, v1 = oacc[nt][1] * inv0;
            __nv_bfloat162 hv = __floats2bfloat162_rn(v0, v1);
            const float l0 = v0 - __bfloat162float(hv.x);
            const float l1 = v1 - __bfloat162float(hv.y);
            *(__nv_bfloat162*)&g_ahi[m0 * DM + n] = hv;
            *(__nv_bfloat162*)&g_alo[m0 * DM + n] = __floats2bfloat162_rn(l0, l1);
        }
        {
            const float v0 = oacc[nt][2] * inv1, v1 = oacc[nt][3] * inv1;
            __nv_bfloat162 hv = __floats2bfloat162_rn(v0, v1);
            const float l0 = v0 - __bfloat162float(hv.x);
            const float l1 = v1 - __bfloat162float(hv.y);
            *(__nv_bfloat162*)&g_ahi[m1 * DM + n] = hv;
            *(__nv_bfloat162*)&g_alo[m1 * DM + n] = __floats2bfloat162_rn(l0, l1);
        }
    }
}

// ============================================================
// residual + LayerNorm (float4 vectorized)
// ============================================================
__global__ __launch_bounds__(256)
void ln_kernel(const float* __restrict__ P, const float* __restrict__ X,
               const float* __restrict__ gamma, const float* __restrict__ beta,
               float* __restrict__ out) {
    __shared__ float red[9];
    const int row = blockIdx.x;
    const int tid = threadIdx.x;
    const float4 pv = ((const float4*)(P + (size_t)row * DM))[tid];
    const float4 xv = ((const float4*)(X + (size_t)row * DM))[tid];

    float y[4] = { pv.x + xv.x, pv.y + xv.y, pv.z + xv.z, pv.w + xv.w };
    float sum = y[0] + y[1] + y[2] + y[3];
    for (int o = 16; o; o >>= 1) sum += __shfl_xor_sync(0xffffffffu, sum, o);
    const int w = tid >> 5, l = tid & 31;
    if (l == 0) red[w] = sum;
    __syncthreads();
    if (w == 0) {
        float t = (l < 8) ? red[l] : 0.f;
        for (int o = 4; o; o >>= 1) t += __shfl_xor_sync(0xffffffffu, t, o);
        if (l == 0) red[8] = t;
    }
    __syncthreads();
    const float mu = red[8] * (1.f / DM);
    __syncthreads();

    float vs = 0.f;
#pragma unroll
    for (int u = 0; u < 4; u++) { const float d = y[u] - mu; vs += d * d; }
    for (int o = 16; o; o >>= 1) vs += __shfl_xor_sync(0xffffffffu, vs, o);
    if (l == 0) red[w] = vs;
    __syncthreads();
    if (w == 0) {
        float t = (l < 8) ? red[l] : 0.f;
        for (int o = 4; o; o >>= 1) t += __shfl_xor_sync(0xffffffffu, t, o);
        if (l == 0) red[8] = t;
    }
    __syncthreads();
    const float var = red[8] * (1.f / DM);
    const float inv = rsqrtf(var + 1e-5f);

    const float4 gv = ((const float4*)gamma)[tid];
    const float4 bv = ((const float4*)beta)[tid];
    float4 ov;
    ov.x = (y[0] - mu) * inv * gv.x + bv.x;
    ov.y = (y[1] - mu) * inv * gv.y + bv.y;
    ov.z = (y[2] - mu) * inv * gv.z + bv.z;
    ov.w = (y[3] - mu) * inv * gv.w + bv.w;
    ((float4*)(out + (size_t)row * DM))[tid] = ov;
}

// ============================================================
extern "C" void kernel_launch(void* const* d_in, const int* in_sizes, int n_in,
                              void* d_out, int out_size) {
    const float* x     = (const float*)d_in[0];
    const float* wq    = (const float*)d_in[1];
    const float* wk    = (const float*)d_in[2];
    const float* wv    = (const float*)d_in[3];
    const float* wo    = (const float*)d_in[4];
    const float* gamma = (const float*)d_in[5];
    const float* beta  = (const float*)d_in[6];
    float* out = (float*)d_out;

    void *pQh, *pQl, *pKh, *pKl, *pVh, *pVl;
    void *pxhi, *pxlo, *pahi, *palo, *pwhi, *pwlo, *pP;
    cudaGetSymbolAddress(&pQh, g_Qhi);  cudaGetSymbolAddress(&pQl, g_Qlo);
    cudaGetSymbolAddress(&pKh, g_Khi);  cudaGetSymbolAddress(&pKl, g_Klo);
    cudaGetSymbolAddress(&pVh, g_Vhi);  cudaGetSymbolAddress(&pVl, g_Vlo);
    cudaGetSymbolAddress(&pxhi, g_xhi); cudaGetSymbolAddress(&pxlo, g_xlo);
    cudaGetSymbolAddress(&pahi, g_ahi); cudaGetSymbolAddress(&palo, g_alo);
    cudaGetSymbolAddress(&pwhi, g_wThi); cudaGetSymbolAddress(&pwlo, g_wTlo);
    cudaGetSymbolAddress(&pP, g_proj);

    bf16* xhi = (bf16*)pxhi;  bf16* xlo = (bf16*)pxlo;
    bf16* ahi = (bf16*)pahi;  bf16* alo = (bf16*)palo;
    bf16* whi = (bf16*)pwhi;  bf16* wlo = (bf16*)pwlo;

    // conversions
    cvt_hilo<<<(MROWS * DM) / 256, 256>>>(x, xhi, xlo);
    cvt_wT<<<(DM * DM) / 256, 256>>>(wq, whi + 0 * (size_t)DM * DM, wlo + 0 * (size_t)DM * DM);
    cvt_wT<<<(DM * DM) / 256, 256>>>(wk, whi + 1 * (size_t)DM * DM, wlo + 1 * (size_t)DM * DM);
    cvt_wT<<<(DM * DM) / 256, 256>>>(wv, whi + 2 * (size_t)DM * DM, wlo + 2 * (size_t)DM * DM);
    cvt_wT<<<(DM * DM) / 256, 256>>>(wo, whi + 3 * (size_t)DM * DM, wlo + 3 * (size_t)DM * DM);

    const int gemm_smem = 2 * 40960;   // 80 KB
    cudaFuncSetAttribute(mma_gemm<0>, cudaFuncAttributeMaxDynamicSharedMemorySize, gemm_smem);
    cudaFuncSetAttribute(mma_gemm<1>, cudaFuncAttributeMaxDynamicSharedMemorySize, gemm_smem);

    const dim3 gdim(DM / 128, MROWS / 128);   // (8, 32)
    mma_gemm<1><<<gdim, 256, gemm_smem>>>(xhi, xlo, whi + 0 * (size_t)DM * DM, wlo + 0 * (size_t)DM * DM,
                                          nullptr, (bf16*)pQh, (bf16*)pQl);
    mma_gemm<1><<<gdim, 256, gemm_smem>>>(xhi, xlo, whi + 1 * (size_t)DM * DM, wlo + 1 * (size_t)DM * DM,
                                          nullptr, (bf16*)pKh, (bf16*)pKl);
    mma_gemm<1><<<gdim, 256, gemm_smem>>>(xhi, xlo, whi + 2 * (size_t)DM * DM, wlo + 2 * (size_t)DM * DM,
                                          nullptr, (bf16*)pVh, (bf16*)pVl);

    const int attn_smem = 110592;      // Qhi/Qlo (36864) + 2 KV bufs (73728)
    cudaFuncSetAttribute(attn_kernel, cudaFuncAttributeMaxDynamicSharedMemorySize, attn_smem);
    attn_kernel<<<dim3(S_LEN / 128, BATCH * NH), 256, attn_smem>>>();

    mma_gemm<0><<<gdim, 256, gemm_smem>>>(ahi, alo, whi + 3 * (size_t)DM * DM, wlo + 3 * (size_t)DM * DM,
                                          (float*)pP, nullptr, nullptr);

    ln_kernel<<<MROWS, 256>>>((const float*)pP, x, gamma, beta, out);
}

// round 11
// speedup vs baseline: 2.6731x; 1.1039x over previous
#include <cuda_runtime.h>
#include <cuda_bf16.h>
#include <cstdint>
#include <math.h>

#define S_LEN 2048
#define DM    1024
#define NH    16
#define DH    64
#define BATCH 2
#define MROWS (BATCH * S_LEN)   // 4096
#define QKV_STRIDE ((size_t)MROWS * DM)

using bf16 = __nv_bfloat16;

// ================= helpers =================
__device__ __forceinline__ uint32_t smem_to_u32(const void* p) {
    uint32_t a;
    asm("{ .reg .u64 t; cvta.to.shared.u64 t, %1; cvt.u32.u64 %0, t; }" : "=r"(a) : "l"(p));
    return a;
}
__device__ __forceinline__ void cp_async16(uint32_t saddr, const void* gaddr) {
    asm volatile("cp.async.cg.shared.global [%0], [%1], 16;" :: "r"(saddr), "l"(gaddr));
}
__device__ __forceinline__ void ldsm_x4(uint32_t* r, uint32_t addr) {
    asm volatile("ldmatrix.sync.aligned.m8n8.x4.shared.b16 {%0,%1,%2,%3}, [%4];"
                 : "=r"(r[0]), "=r"(r[1]), "=r"(r[2]), "=r"(r[3]) : "r"(addr));
}
__device__ __forceinline__ void ldsm_x2(uint32_t* r, uint32_t addr) {
    asm volatile("ldmatrix.sync.aligned.m8n8.x2.shared.b16 {%0,%1}, [%2];"
                 : "=r"(r[0]), "=r"(r[1]) : "r"(addr));
}
__device__ __forceinline__ void ldsm_x2t(uint32_t* r, uint32_t addr) {
    asm volatile("ldmatrix.sync.aligned.m8n8.x2.trans.shared.b16 {%0,%1}, [%2];"
                 : "=r"(r[0]), "=r"(r[1]) : "r"(addr));
}
// D += A(16x16 bf16, row) * B(16x8 bf16, col), fp32 acc
__device__ __forceinline__ void mma16816(float* d, const uint32_t* a, const uint32_t* b) {
    asm volatile(
        "mma.sync.aligned.m16n8k16.row.col.f32.bf16.bf16.f32 "
        "{%0,%1,%2,%3}, {%4,%5,%6,%7}, {%8,%9}, {%0,%1,%2,%3};\n"
        : "+f"(d[0]), "+f"(d[1]), "+f"(d[2]), "+f"(d[3])
        : "r"(a[0]), "r"(a[1]), "r"(a[2]), "r"(a[3]), "r"(b[0]), "r"(b[1]));
}
// pack two fp32 into bf16x2 (hi part) plus residual bf16x2 (lo part)
__device__ __forceinline__ void pack_pair(float p0, float p1, uint32_t& hi, uint32_t& lo) {
    __nv_bfloat162 h = __floats2bfloat162_rn(p0, p1);   // .x = p0 (low half)
    hi = *(uint32_t*)&h;
    const float l0 = p0 - __bfloat162float(h.x);
    const float l1 = p1 - __bfloat162float(h.y);
    __nv_bfloat162 l = __floats2bfloat162_rn(l0, l1);
    lo = *(uint32_t*)&l;
}

// ---- scratch (device globals) ----
__device__ bf16 g_QKVhi[3][BATCH * NH * S_LEN * DH];   // [B,H,S,Dh] x {Q,K,V}
__device__ bf16 g_QKVlo[3][BATCH * NH * S_LEN * DH];
__device__ bf16 g_xhi[MROWS * DM];
__device__ bf16 g_xlo[MROWS * DM];
__device__ bf16 g_ahi[MROWS * DM];
__device__ bf16 g_alo[MROWS * DM];
__device__ bf16 g_wThi[4][DM * DM];   // q,k,v,o  ([N,K] layout)
__device__ bf16 g_wTlo[4][DM * DM];
__device__ float g_proj[MROWS * DM];

// ============================================================
// fp32 -> bf16 hi/lo split (same layout)
// ============================================================
__global__ __launch_bounds__(256)
void cvt_hilo(const float* __restrict__ in, bf16* __restrict__ hi,
              bf16* __restrict__ lo) {
    const int i = blockIdx.x * 256 + threadIdx.x;
    const float v = in[i];
    const bf16 h = __float2bfloat16(v);
    hi[i] = h;
    lo[i] = __float2bfloat16(v - __bfloat162float(h));
}

// all 4 weights [K=1024, N=1024] fp32 -> wT hi/lo [N, K] bf16, smem transpose
__global__ __launch_bounds__(256)
void cvt_wT_all(const float* __restrict__ w0, const float* __restrict__ w1,
                const float* __restrict__ w2, const float* __restrict__ w3,
                bf16* __restrict__ hiT, bf16* __restrict__ loT) {
    __shared__ float t[32][33];
    const float* ws[4] = { w0, w1, w2, w3 };
    const int z = blockIdx.z;
    const float* w = ws[z];
    const int bn = blockIdx.x * 32, bk = blockIdx.y * 32;
    const int tx = threadIdx.x, ty = threadIdx.y;   // block (32, 8)
#pragma unroll
    for (int i = 0; i < 32; i += 8)
        t[ty + i][tx] = w[(size_t)(bk + ty + i) * DM + bn + tx];
    __syncthreads();
    const size_t zoff = (size_t)z * DM * DM;
#pragma unroll
    for (int i = 0; i < 32; i += 8) {
        const float v = t[tx][ty + i];                 // = w[bk+tx][bn+ty+i]
        const bf16 h = __float2bfloat16(v);
        const size_t o = zoff + (size_t)(bn + ty + i) * DM + bk + tx;
        hiT[o] = h;
        loT[o] = __float2bfloat16(v - __bfloat162float(h));
    }
}

// ============================================================
// HMMA split-bf16 GEMM: C[4096,1024] = A @ B^T (B stored [N,K]).
// D = Ahi*Bhi + Ahi*Blo + Alo*Bhi, fp32 accumulate.
// 128x128 block tile, K-tile 32, 8 warps (4x2), warp 32x64.
// cp.async double buffer. smem row stride 40 bf16 (80B).
// blockIdx.z selects weight slot (and output slot in MODE 1).
// MODE 0: fp32 C row-major.  MODE 1: bf16 hi/lo scatter to [B,H,S,Dh].
// __launch_bounds__(256,2): 2 CTAs/SM.
// ============================================================
template <int MODE>
__global__ __launch_bounds__(256, 2)
void mma_gemm(const bf16* __restrict__ Ahi, const bf16* __restrict__ Alo,
              const bf16* __restrict__ BhiB, const bf16* __restrict__ BloB,
              float* __restrict__ C, bf16* __restrict__ ChiB, bf16* __restrict__ CloB)
{
    extern __shared__ char smd[];
    const int tid = threadIdx.x;
    const int lane = tid & 31, wid = tid >> 5;
    const int wm = wid & 3, wn = wid >> 2;            // 4 x 2 warp grid
    const int m0 = blockIdx.y * 128, n0 = blockIdx.x * 128;
    const int z = blockIdx.z;
    const uint32_t sb = smem_to_u32(smd);

    const bf16* Bhi = BhiB + (size_t)z * DM * DM;
    const bf16* Blo = BloB + (size_t)z * DM * DM;
    const bf16* srcs[4] = { Ahi + (size_t)m0 * DM, Alo + (size_t)m0 * DM,
                            Bhi + (size_t)n0 * DM, Blo + (size_t)n0 * DM };

    auto prefetch = [&](int kt) {
        const uint32_t bb = sb + (kt & 1) * 40960;
        const int k0 = kt * 32;
#pragma unroll
        for (int t = 0; t < 4; t++) {
            const bf16* s = srcs[t] + k0;
            const uint32_t tb = bb + t * 10240;
#pragma unroll
            for (int i = 0; i < 2; i++) {
                const int idx = i * 256 + tid;
                const int r = idx >> 2, c = idx & 3;
                cp_async16(tb + r * 80 + c * 16, s + (size_t)r * DM + c * 8);
            }
        }
        asm volatile("cp.async.commit_group;");
    };

    prefetch(0);
    prefetch(1);

    float acc[2][8][4];
#pragma unroll
    for (int mt = 0; mt < 2; mt++)
#pragma unroll
        for (int nt = 0; nt < 8; nt++)
#pragma unroll
            for (int e = 0; e < 4; e++) acc[mt][nt][e] = 0.f;

    const int KT = DM / 32;   // 32
    for (int kt = 0; kt < KT; kt++) {
        if (kt == KT - 1) asm volatile("cp.async.wait_group 0;" ::: "memory");
        else              asm volatile("cp.async.wait_group 1;" ::: "memory");
        __syncthreads();
        const uint32_t bb = sb + (kt & 1) * 40960;
#pragma unroll
        for (int ks = 0; ks < 2; ks++) {
            const int kk = ks * 16;
            uint32_t ah[2][4], al[2][4];
            const uint32_t acol = (uint32_t)(kk + (lane >> 4) * 8) * 2;
#pragma unroll
            for (int mt = 0; mt < 2; mt++) {
                const uint32_t ra = bb + (uint32_t)(wm * 32 + mt * 16 + (lane & 15)) * 80 + acol;
                ldsm_x4(ah[mt], ra);
                ldsm_x4(al[mt], ra + 10240);
            }
#pragma unroll
            for (int nt = 0; nt < 8; nt++) {
                uint32_t bhf[2], blf[2];
                const uint32_t rb = bb + 20480
                    + (uint32_t)(wn * 64 + nt * 8 + (lane & 7)) * 80
                    + (uint32_t)(kk + ((lane >> 3) & 1) * 8) * 2;
                ldsm_x2(bhf, rb);
                ldsm_x2(blf, rb + 10240);
#pragma unroll
                for (int mt = 0; mt < 2; mt++) {
                    mma16816(acc[mt][nt], ah[mt], bhf);
                    mma16816(acc[mt][nt], ah[mt], blf);
                    mma16816(acc[mt][nt], al[mt], bhf);
                }
            }
        }
        __syncthreads();
        if (kt + 2 < KT) prefetch(kt + 2);
    }

    bf16* Chi = (MODE == 1) ? ChiB + (size_t)z * QKV_STRIDE : nullptr;
    bf16* Clo = (MODE == 1) ? CloB + (size_t)z * QKV_STRIDE : nullptr;

#pragma unroll
    for (int mt = 0; mt < 2; mt++)
#pragma unroll
    for (int nt = 0; nt < 8; nt++) {
        const int r0 = m0 + wm * 32 + mt * 16 + (lane >> 2);
        const int c0 = n0 + wn * 64 + nt * 8 + (lane & 3) * 2;
#pragma unroll
        for (int e = 0; e < 4; e++) {
            const int r = r0 + (e >> 1) * 8;
            const int c = c0 + (e & 1);
            const float v = acc[mt][nt][e];
            if (MODE == 0) {
                C[(size_t)r * DM + c] = v;
            } else {
                const int b = r >> 11, s = r & 2047;
                const int h = c >> 6, d = c & 63;
                const size_t o = (((size_t)(b * NH + h)) * S_LEN + s) * DH + d;
                const bf16 hv = __float2bfloat16(v);
                Chi[o] = hv;
                Clo[o] = __float2bfloat16(v - __bfloat162float(hv));
            }
        }
    }
}

// ============================================================
// FA2-style HMMA flash attention: BM=128, BN=64, Dh=64, 8 warps.
// Each warp: 16 query rows x full 64 kv cols x full 64 d.
// S acc kept in registers; softmax via quad shfl; P repacked from
// C-frag into A-frag in registers (no S/P smem round trip).
// 3-pass hi/lo split for both QK^T and PV.
// ============================================================
__global__ __launch_bounds__(256)
void attn_kernel() {
    extern __shared__ char smd[];
    const int tid = threadIdx.x, lane = tid & 31, wid = tid >> 5;
    const int qt = (int)gridDim.x - 1 - (int)blockIdx.x;   // heavy tiles first
    const int bh = blockIdx.y;
    const int b = bh >> 4, h = bh & 15;
    const int q0 = qt * 128;
    const int groupID = lane >> 2, tid4 = lane & 3;
    const uint32_t sb = smem_to_u32(smd);
    const uint32_t QHo = 0;                        // 128 x 144B
    const uint32_t KV0 = 36864, KVSZ = 36864;      // per buf: Khi,Klo,Vhi,Vlo (64x144B each)
    const int nkt = 2 * qt + 2;

    const size_t base_off = (size_t)bh * S_LEN * DH;

    // Q hi/lo loads (group 0, together with KV tile 0)
    {
        const bf16* qh = g_QKVhi[0] + base_off + (size_t)q0 * DH;
        const bf16* ql = g_QKVlo[0] + base_off + (size_t)q0 * DH;
#pragma unroll
        for (int i = 0; i < 4; i++) {
            const int idx = i * 256 + tid;
            const int r = idx >> 3, c = idx & 7;
            cp_async16(sb + QHo + r * 144 + c * 16, qh + r * 64 + c * 8);
            cp_async16(sb + QHo + 18432 + r * 144 + c * 16, ql + r * 64 + c * 8);
        }
    }
    auto kvload = [&](int kt) {
        const uint32_t bb = sb + KV0 + (kt & 1) * KVSZ;
        const size_t off = base_off + (size_t)kt * 64 * DH;
        const bf16* srcs[4] = { g_QKVhi[1] + off, g_QKVlo[1] + off,
                                g_QKVhi[2] + off, g_QKVlo[2] + off };
#pragma unroll
        for (int t = 0; t < 4; t++) {
            const uint32_t tb = bb + t * 9216;
            const bf16* s = srcs[t];
#pragma unroll
            for (int i = 0; i < 2; i++) {
                const int idx = i * 256 + tid;
                const int r = idx >> 3, c = idx & 7;
                cp_async16(tb + r * 144 + c * 16, s + r * 64 + c * 8);
            }
        }
        asm volatile("cp.async.commit_group;");
    };
    kvload(0);           // G0 = Q + KV0
    kvload(1);           // G1 = KV1   (nkt >= 2 always)
    asm volatile("cp.async.wait_group 1;" ::: "memory");
    __syncthreads();

    // Hoist Q fragments for the whole kernel
    uint32_t qhf[4][4], qlf[4][4];
#pragma unroll
    for (int ks = 0; ks < 4; ks++) {
        const uint32_t ra = sb + QHo + (uint32_t)(wid * 16 + (lane & 15)) * 144
                            + (uint32_t)(ks * 16 + (lane >> 4) * 8) * 2;
        ldsm_x4(qhf[ks], ra);
        ldsm_x4(qlf[ks], ra + 18432);
    }

    float rm0 = -1e30f, rm1 = -1e30f, rl0 = 0.f, rl1 = 0.f;
    float oacc[8][4];
#pragma unroll
    for (int nt = 0; nt < 8; nt++)
#pragma unroll
        for (int e = 0; e < 4; e++) oacc[nt][e] = 0.f;

    for (int kt = 0; kt < nkt; kt++) {
        const uint32_t kb = sb + KV0 + (kt & 1) * KVSZ;
        const uint32_t vb = kb + 18432;

        // ---- S = Q @ K^T (3-pass split), 16x64 per warp ----
        float sacc[8][4];
#pragma unroll
        for (int nt = 0; nt < 8; nt++)
#pragma unroll
            for (int e = 0; e < 4; e++) sacc[nt][e] = 0.f;

#pragma unroll
        for (int ks = 0; ks < 4; ks++) {
#pragma unroll
            for (int nt = 0; nt < 8; nt++) {
                uint32_t khf[2], klf[2];
                const uint32_t rb = kb + (uint32_t)(nt * 8 + (lane & 7)) * 144
                                    + (uint32_t)(ks * 16 + ((lane >> 3) & 1) * 8) * 2;
                ldsm_x2(khf, rb);
                ldsm_x2(klf, rb + 9216);
                mma16816(sacc[nt], qhf[ks], khf);
                mma16816(sacc[nt], qhf[ks], klf);
                mma16816(sacc[nt], qlf[ks], khf);
            }
        }

        // ---- scale + causal mask (in registers) ----
        const int row0 = q0 + wid * 16 + groupID;
#pragma unroll
        for (int nt = 0; nt < 8; nt++) {
            const int c0 = kt * 64 + nt * 8 + tid4 * 2;
#pragma unroll
            for (int e = 0; e < 4; e++) {
                const int col = c0 + (e & 1);
                const int row = row0 + ((e >> 1) << 3);
                const float v = sacc[nt][e] * 0.125f;
                sacc[nt][e] = (col > row) ? -10000000.0f : v;
            }
        }

        // ---- online softmax (quad shfl, rows groupID and groupID+8) ----
        float mx0 = rm0, mx1 = rm1;
#pragma unroll
        for (int nt = 0; nt < 8; nt++) {
            mx0 = fmaxf(mx0, fmaxf(sacc[nt][0], sacc[nt][1]));
            mx1 = fmaxf(mx1, fmaxf(sacc[nt][2], sacc[nt][3]));
        }
        mx0 = fmaxf(mx0, __shfl_xor_sync(0xffffffffu, mx0, 1));
        mx0 = fmaxf(mx0, __shfl_xor_sync(0xffffffffu, mx0, 2));
        mx1 = fmaxf(mx1, __shfl_xor_sync(0xffffffffu, mx1, 1));
        mx1 = fmaxf(mx1, __shfl_xor_sync(0xffffffffu, mx1, 2));
        float s0 = 0.f, s1 = 0.f;
#pragma unroll
        for (int nt = 0; nt < 8; nt++) {
            sacc[nt][0] = __expf(sacc[nt][0] - mx0); s0 += sacc[nt][0];
            sacc[nt][1] = __expf(sacc[nt][1] - mx0); s0 += sacc[nt][1];
            sacc[nt][2] = __expf(sacc[nt][2] - mx1); s1 += sacc[nt][2];
            sacc[nt][3] = __expf(sacc[nt][3] - mx1); s1 += sacc[nt][3];
        }
        s0 += __shfl_xor_sync(0xffffffffu, s0, 1);
        s0 += __shfl_xor_sync(0xffffffffu, s0, 2);
        s1 += __shfl_xor_sync(0xffffffffu, s1, 1);
        s1 += __shfl_xor_sync(0xffffffffu, s1, 2);
        const float sc0 = __expf(rm0 - mx0), sc1 = __expf(rm1 - mx1);
        rl0 = rl0 * sc0 + s0;  rl1 = rl1 * sc1 + s1;
        rm0 = mx0;  rm1 = mx1;
#pragma unroll
        for (int nt = 0; nt < 8; nt++) {
            oacc[nt][0] *= sc0; oacc[nt][1] *= sc0;
            oacc[nt][2] *= sc1; oacc[nt][3] *= sc1;
        }

        // ---- O += P @ V: repack C-frag -> A-frag in registers ----
#pragma unroll
        for (int j = 0; j < 4; j++) {
            uint32_t ph[4], pl[4];
            pack_pair(sacc[2 * j][0],     sacc[2 * j][1],     ph[0], pl[0]);
            pack_pair(sacc[2 * j][2],     sacc[2 * j][3],     ph[1], pl[1]);
            pack_pair(sacc[2 * j + 1][0], sacc[2 * j + 1][1], ph[2], pl[2]);
            pack_pair(sacc[2 * j + 1][2], sacc[2 * j + 1][3], ph[3], pl[3]);
#pragma unroll
            for (int nt = 0; nt < 8; nt++) {
                uint32_t vhf[2], vlf[2];
                const uint32_t rb = vb + (uint32_t)(j * 16 + (lane & 15)) * 144
                                    + (uint32_t)(nt * 8) * 2;
                ldsm_x2t(vhf, rb);
                ldsm_x2t(vlf, rb + 9216);
                mma16816(oacc[nt], ph, vhf);
                mma16816(oacc[nt], ph, vlf);
                mma16816(oacc[nt], pl, vhf);
            }
        }

        // ---- pipeline next KV tile ----
        if (kt + 1 < nkt) {
            __syncthreads();   // all warps done reading buf (kt&1)
            if (kt + 2 < nkt) {
                kvload(kt + 2);
                asm volatile("cp.async.wait_group 1;" ::: "memory");
            } else {
                asm volatile("cp.async.wait_group 0;" ::: "memory");
            }
        }
    }

    // ---- epilogue: O / l  -> bf16 hi/lo merged-head layout ----
    const float inv0 = 1.f / rl0, inv1 = 1.f / rl1;
    const size_t m0 = (size_t)b * S_LEN + q0 + wid * 16 + groupID;
    const size_t m1 = m0 + 8;
#pragma unroll
    for (int nt = 0; nt < 8; nt++) {
        const int n = h * 64 + nt * 8 + tid4 * 2;
        {
            const float v0 = oacc[nt][0] * inv0, v1 = oacc[nt][1] * inv0;
            __nv_bfloat162 hv = __floats2bfloat162_rn(v0, v1);
            const float l0 = v0 - __bfloat162float(hv.x);
            const float l1 = v1 - __bfloat162float(hv.y);
            *(__nv_bfloat162*)&g_ahi[m0 * DM + n] = hv;
            *(__nv_bfloat162*)&g_alo[m0 * DM + n] = __floats2bfloat162_rn(l0, l1);
        }
        {
            const float v0 = oacc[nt][2] * inv1, v1 = oacc[nt][3] * inv1;
            __nv_bfloat162 hv = __floats2bfloat162_rn(v0, v1);
            const float l0 = v0 - __bfloat162float(hv.x);
            const float l1 = v1 - __bfloat162float(hv.y);
            *(__nv_bfloat162*)&g_ahi[m1 * DM + n] = hv;
            *(__nv_bfloat162*)&g_alo[m1 * DM + n] = __floats2bfloat162_rn(l0, l1);
        }
    }
}

// ============================================================
// residual + LayerNorm (float4 vectorized)
// ============================================================
__global__ __launch_bounds__(256)
void ln_kernel(const float* __restrict__ P, const float* __restrict__ X,
               const float* __restrict__ gamma, const float* __restrict__ beta,
               float* __restrict__ out) {
    __shared__ float red[9];
    const int row = blockIdx.x;
    const int tid = threadIdx.x;
    const float4 pv = ((const float4*)(P + (size_t)row * DM))[tid];
    const float4 xv = ((const float4*)(X + (size_t)row * DM))[tid];

    float y[4] = { pv.x + xv.x, pv.y + xv.y, pv.z + xv.z, pv.w + xv.w };
    float sum = y[0] + y[1] + y[2] + y[3];
    for (int o = 16; o; o >>= 1) sum += __shfl_xor_sync(0xffffffffu, sum, o);
    const int w = tid >> 5, l = tid & 31;
    if (l == 0) red[w] = sum;
    __syncthreads();
    if (w == 0) {
        float t = (l < 8) ? red[l] : 0.f;
        for (int o = 4; o; o >>= 1) t += __shfl_xor_sync(0xffffffffu, t, o);
        if (l == 0) red[8] = t;
    }
    __syncthreads();
    const float mu = red[8] * (1.f / DM);
    __syncthreads();

    float vs = 0.f;
#pragma unroll
    for (int u = 0; u < 4; u++) { const float d = y[u] - mu; vs += d * d; }
    for (int o = 16; o; o >>= 1) vs += __shfl_xor_sync(0xffffffffu, vs, o);
    if (l == 0) red[w] = vs;
    __syncthreads();
    if (w == 0) {
        float t = (l < 8) ? red[l] : 0.f;
        for (int o = 4; o; o >>= 1) t += __shfl_xor_sync(0xffffffffu, t, o);
        if (l == 0) red[8] = t;
    }
    __syncthreads();
    const float var = red[8] * (1.f / DM);
    const float inv = rsqrtf(var + 1e-5f);

    const float4 gv = ((const float4*)gamma)[tid];
    const float4 bv = ((const float4*)beta)[tid];
    float4 ov;
    ov.x = (y[0] - mu) * inv * gv.x + bv.x;
    ov.y = (y[1] - mu) * inv * gv.y + bv.y;
    ov.z = (y[2] - mu) * inv * gv.z + bv.z;
    ov.w = (y[3] - mu) * inv * gv.w + bv.w;
    ((float4*)(out + (size_t)row * DM))[tid] = ov;
}

// ============================================================
extern "C" void kernel_launch(void* const* d_in, const int* in_sizes, int n_in,
                              void* d_out, int out_size) {
    const float* x     = (const float*)d_in[0];
    const float* wq    = (const float*)d_in[1];
    const float* wk    = (const float*)d_in[2];
    const float* wv    = (const float*)d_in[3];
    const float* wo    = (const float*)d_in[4];
    const float* gamma = (const float*)d_in[5];
    const float* beta  = (const float*)d_in[6];
    float* out = (float*)d_out;

    void *pQKVh, *pQKVl;
    void *pxhi, *pxlo, *pahi, *palo, *pwhi, *pwlo, *pP;
    cudaGetSymbolAddress(&pQKVh, g_QKVhi);
    cudaGetSymbolAddress(&pQKVl, g_QKVlo);
    cudaGetSymbolAddress(&pxhi, g_xhi); cudaGetSymbolAddress(&pxlo, g_xlo);
    cudaGetSymbolAddress(&pahi, g_ahi); cudaGetSymbolAddress(&palo, g_alo);
    cudaGetSymbolAddress(&pwhi, g_wThi); cudaGetSymbolAddress(&pwlo, g_wTlo);
    cudaGetSymbolAddress(&pP, g_proj);

    bf16* xhi = (bf16*)pxhi;  bf16* xlo = (bf16*)pxlo;
    bf16* ahi = (bf16*)pahi;  bf16* alo = (bf16*)palo;
    bf16* whi = (bf16*)pwhi;  bf16* wlo = (bf16*)pwlo;

    // conversions
    cvt_hilo<<<(MROWS * DM) / 256, 256>>>(x, xhi, xlo);
    cvt_wT_all<<<dim3(32, 32, 4), dim3(32, 8)>>>(wq, wk, wv, wo, whi, wlo);

    const int gemm_smem = 2 * 40960;   // 80 KB
    cudaFuncSetAttribute(mma_gemm<0>, cudaFuncAttributeMaxDynamicSharedMemorySize, gemm_smem);
    cudaFuncSetAttribute(mma_gemm<1>, cudaFuncAttributeMaxDynamicSharedMemorySize, gemm_smem);

    // fused QKV projections: grid.z = weight/output slot
    mma_gemm<1><<<dim3(DM / 128, MROWS / 128, 3), 256, gemm_smem>>>(
        xhi, xlo, whi, wlo, nullptr, (bf16*)pQKVh, (bf16*)pQKVl);

    const int attn_smem = 110592;      // Qhi/Qlo (36864) + 2 KV bufs (73728)
    cudaFuncSetAttribute(attn_kernel, cudaFuncAttributeMaxDynamicSharedMemorySize, attn_smem);
    attn_kernel<<<dim3(S_LEN / 128, BATCH * NH), 256, attn_smem>>>();

    // output projection (weight slot 3)
    mma_gemm<0><<<dim3(DM / 128, MROWS / 128, 1), 256, gemm_smem>>>(
        ahi, alo, whi + 3 * (size_t)DM * DM, wlo + 3 * (size_t)DM * DM,
        (float*)pP, nullptr, nullptr);

    ln_kernel<<<MROWS, 256>>>((const float*)pP, x, gamma, beta, out);
}